// round 15
// baseline (speedup 1.0000x reference)
#include <cuda_runtime.h>
#include <cuda_bf16.h>
#include <cstdint>
#include <cstddef>

// RNN_5188320494079: N=64, T=1024, D=256, H=256, fp32.
// Inputs: x[N,T,D], h0[N,H], Wx[D,H], Wh[H,H], b[H]. Output: [N,T,H].
//
// Kernel 1: Out = x @ Wx + b (packed-f32x2 SGEMM, in-place into d_out).
// Kernel 2: partial-sum-exchange cluster scan, 512 thr, cluster(2) = batch n.
//   Each CTA reads ONLY its own 128 h rows (produced locally) and computes
//   partials for ALL 256 columns -> no fabric wait before the FMA. Partials
//   for the peer's 128 columns ship as 64 aggregated b64 st.async sends
//   right after the FMA (fabric overlaps finalizer compute). Double-buffered
//   tx barriers, one __syncthreads per step, double-buffered hbuf.

#define RNN_N 64
#define RNN_T 1024
#define RNN_D 256
#define RNN_H 256
#define HHALF 128

typedef unsigned long long ull;

__device__ __forceinline__ void ffma2(ull& d, ull a, ull b) {
    asm("fma.rn.f32x2 %0, %1, %2, %0;" : "+l"(d) : "l"(a), "l"(b));
}
__device__ __forceinline__ float2 u2f(ull u) {
    float2 f;
    asm("mov.b64 {%0, %1}, %2;" : "=f"(f.x), "=f"(f.y) : "l"(u));
    return f;
}
__device__ __forceinline__ ull f2u(float a, float b) {
    ull u;
    asm("mov.b64 %0, {%1, %2};" : "=l"(u) : "f"(a), "f"(b));
    return u;
}
__device__ __forceinline__ uint32_t smem_u32(const void* p) {
    uint32_t a;
    asm("{ .reg .u64 t; cvta.to.shared.u64 t, %1; cvt.u32.u64 %0, t; }"
        : "=r"(a) : "l"(p));
    return a;
}
__device__ __forceinline__ void mbar_wait(uint32_t addr, uint32_t parity) {
    asm volatile(
        "{\n\t.reg .pred P;\n\t"
        "WL%=:\n\t"
        "mbarrier.try_wait.parity.acquire.cta.shared::cta.b64 P, [%0], %1, 0x989680;\n\t"
        "@P bra.uni WD%=;\n\t"
        "bra.uni WL%=;\n\t"
        "WD%=:\n\t}"
        :: "r"(addr), "r"(parity) : "memory");
}
__device__ __forceinline__ void mbar_expect(uint32_t addr, uint32_t bytes) {
    asm volatile("mbarrier.arrive.expect_tx.shared::cta.b64 _, [%0], %1;"
                 :: "r"(addr), "r"(bytes) : "memory");
}

// ---------------------------------------------------------------------------
// Kernel 1: smem-tiled SGEMM, BM=128 BN=128 BK=16, 256 thr, f32x2 micro-kernel.
// (unchanged — FFMA2-bound, ~190us)
// ---------------------------------------------------------------------------
__global__ __launch_bounds__(256, 2)
void gemm_xw_kernel(const float* __restrict__ X, const float* __restrict__ Wx,
                    const float* __restrict__ bias, float* __restrict__ Out) {
    __shared__ __align__(16) float2 Asd[16][128];
    __shared__ __align__(16) float  Bs[16][128];

    const int tid = threadIdx.x;
    const int tx = tid & 15;
    const int ty = tid >> 4;
    const int m0 = blockIdx.x * 128;
    const int n0 = blockIdx.y * 128;

    const int a_row = tid >> 2;
    const int a_col = (tid & 3) << 2;
    const int b_row = tid >> 5;
    const int b_col = (tid & 31) << 2;

    ull acc[8][4];
#pragma unroll
    for (int i = 0; i < 8; i++)
#pragma unroll
        for (int j = 0; j < 4; j++) acc[i][j] = 0ull;

    const float* Xa0 = &X[(size_t)(m0 + a_row) * RNN_D + a_col];
    const float* Xa1 = &X[(size_t)(m0 + a_row + 64) * RNN_D + a_col];
    const float* Wb0 = &Wx[(size_t)b_row * RNN_H + n0 + b_col];
    const float* Wb1 = &Wx[(size_t)(b_row + 8) * RNN_H + n0 + b_col];

    for (int k0 = 0; k0 < RNN_D; k0 += 16) {
        float4 av0 = __ldcs(reinterpret_cast<const float4*>(Xa0 + k0));
        float4 av1 = __ldcs(reinterpret_cast<const float4*>(Xa1 + k0));
        float4 bv0 = *reinterpret_cast<const float4*>(Wb0 + (size_t)k0 * RNN_H);
        float4 bv1 = *reinterpret_cast<const float4*>(Wb1 + (size_t)k0 * RNN_H);
        __syncthreads();
        Asd[a_col + 0][a_row] = make_float2(av0.x, av0.x);
        Asd[a_col + 1][a_row] = make_float2(av0.y, av0.y);
        Asd[a_col + 2][a_row] = make_float2(av0.z, av0.z);
        Asd[a_col + 3][a_row] = make_float2(av0.w, av0.w);
        Asd[a_col + 0][a_row + 64] = make_float2(av1.x, av1.x);
        Asd[a_col + 1][a_row + 64] = make_float2(av1.y, av1.y);
        Asd[a_col + 2][a_row + 64] = make_float2(av1.z, av1.z);
        Asd[a_col + 3][a_row + 64] = make_float2(av1.w, av1.w);
        *reinterpret_cast<float4*>(&Bs[b_row][b_col]) = bv0;
        *reinterpret_cast<float4*>(&Bs[b_row + 8][b_col]) = bv1;
        __syncthreads();
#pragma unroll
        for (int k = 0; k < 16; k++) {
            const ulonglong2* ad = reinterpret_cast<const ulonglong2*>(&Asd[k][ty * 8]);
            ulonglong2 aa0 = ad[0], aa1 = ad[1], aa2 = ad[2], aa3 = ad[3];
            const ulonglong2* bd = reinterpret_cast<const ulonglong2*>(&Bs[k][tx * 8]);
            ulonglong2 bb0 = bd[0], bb1 = bd[1];
            ull ap[8] = {aa0.x, aa0.y, aa1.x, aa1.y, aa2.x, aa2.y, aa3.x, aa3.y};
            ull bp[4] = {bb0.x, bb0.y, bb1.x, bb1.y};
#pragma unroll
            for (int i = 0; i < 8; i++) {
                ffma2(acc[i][0], ap[i], bp[0]);
                ffma2(acc[i][1], ap[i], bp[1]);
                ffma2(acc[i][2], ap[i], bp[2]);
                ffma2(acc[i][3], ap[i], bp[3]);
            }
        }
    }

    float4 bb0 = *reinterpret_cast<const float4*>(&bias[n0 + tx * 8]);
    float4 bb1 = *reinterpret_cast<const float4*>(&bias[n0 + tx * 8 + 4]);
    float bb[8] = {bb0.x, bb0.y, bb0.z, bb0.w, bb1.x, bb1.y, bb1.z, bb1.w};
#pragma unroll
    for (int i = 0; i < 8; i++) {
        size_t r = (size_t)(m0 + ty * 8 + i) * RNN_H + n0 + tx * 8;
        float2 v0 = u2f(acc[i][0]), v1 = u2f(acc[i][1]);
        float2 v2 = u2f(acc[i][2]), v3 = u2f(acc[i][3]);
        float4 o0 = make_float4(v0.x + bb[0], v0.y + bb[1], v1.x + bb[2], v1.y + bb[3]);
        float4 o1 = make_float4(v2.x + bb[4], v2.y + bb[5], v3.x + bb[6], v3.y + bb[7]);
        *reinterpret_cast<float4*>(&Out[r]) = o0;
        *reinterpret_cast<float4*>(&Out[r + 4]) = o1;
    }
}

// ---------------------------------------------------------------------------
// Kernel 2: partial-exchange cluster scan.
// 512 thr: sc = tid>>1, q = tid&1; global col gc = sc ^ (rank<<7), so
// finalizer threads (own cols) are tids 0..255 and SENDER threads (peer cols)
// are tids 256..511 (wid 8-15 -> hi-wid-first arbiter priority) on BOTH ranks.
// Thread computes partial over own-half rows [own_base+q*64, +64) for col gc
// (Wh slice = 32 packed reg pairs). shfl_xor(1) totals the 128-row partial;
// shfl_down(2) aggregates column pairs; sender lanes (tid&3==0) ship one b64
// per 2 cols -> 64 st.async complete_tx into peer qbuf[t&1] + B[t&1] (512B).
// Finalizers (even tid<256) wait B[t&1] parity (t>>1)&1, re-arm for t+2,
// z = xw + own_partial + qbuf, tanh, store h locally + output.
// One __syncthreads per step; hbuf double-buffered.
// ---------------------------------------------------------------------------
__global__ __launch_bounds__(512, 1) __cluster_dims__(2, 1, 1)
void rnn_scan_kernel(const float* __restrict__ h0,
                     const float* __restrict__ Wh,
                     float* Out) {
    __shared__ __align__(16) float hbuf[2][HHALF];   // own h half, 1KB
    __shared__ __align__(16) float qbuf[2][HHALF];   // peer partials, 1KB
    __shared__ __align__(8)  unsigned long long mbars[2]; // B0, B1

    const int tid = threadIdx.x;
    uint32_t rank;
    asm("mov.u32 %0, %%cluster_ctarank;" : "=r"(rank));
    const uint32_t peer = rank ^ 1u;
    const int n = blockIdx.x >> 1;
    const int sc = tid >> 1;                 // 0..255
    const int q = tid & 1;                   // own-half row split
    const int gc = sc ^ ((int)rank << 7);    // global column
    const int own_base = (int)rank * HHALF;
    const bool is_sender = (sc >= HHALF);    // gc in peer's range
    const int l = sc;                        // finalizer local col (sc<128)
    const int pc = sc - HHALF;               // sender peer-local col
    const int row0 = q * 64;                 // within own half

    const uint32_t mbarB0 = smem_u32((const void*)&mbars[0]);
    const uint32_t mbarB1 = smem_u32((const void*)&mbars[1]);

    if (tid == 0) {
        asm volatile("mbarrier.init.shared.b64 [%0], %1;"
                     :: "r"(mbarB0), "r"(1) : "memory");
        asm volatile("mbarrier.init.shared.b64 [%0], %1;"
                     :: "r"(mbarB1), "r"(1) : "memory");
    }

    // Register Wh slice: rows own_base+row0 .. +63, col gc, 32 packed pairs.
    ull wq[32];
#pragma unroll
    for (int k = 0; k < 32; k++) {
        int r = own_base + row0 + 2 * k;
        wq[k] = f2u(__ldg(&Wh[(size_t)r * RNN_H + gc]),
                    __ldg(&Wh[(size_t)(r + 1) * RNN_H + gc]));
    }

    float* outn = Out + (size_t)n * RNN_T * RNN_H;

    if (tid < HHALF)
        hbuf[0][tid] = h0[(size_t)n * RNN_H + own_base + tid];

    float xw_cur = 0.f;
    uint32_t rq0 = 0, rq1 = 0, rb0 = 0, rb1 = 0;
    if (is_sender && (tid & 3) == 0) {       // aggregation/send lanes, pc even
        uint32_t a0 = smem_u32(&qbuf[0][pc]);
        uint32_t a1 = smem_u32(&qbuf[1][pc]);
        asm("mapa.shared::cluster.u32 %0, %1, %2;" : "=r"(rq0) : "r"(a0), "r"(peer));
        asm("mapa.shared::cluster.u32 %0, %1, %2;" : "=r"(rq1) : "r"(a1), "r"(peer));
        asm("mapa.shared::cluster.u32 %0, %1, %2;" : "=r"(rb0) : "r"(mbarB0), "r"(peer));
        asm("mapa.shared::cluster.u32 %0, %1, %2;" : "=r"(rb1) : "r"(mbarB1), "r"(peer));
    } else if (!is_sender && q == 0) {
        xw_cur = __ldcg(&outn[gc]);
    }
    __syncthreads();
    if (tid == 0) {
        mbar_expect(mbarB0, 512u);   // consumed at t=0
        mbar_expect(mbarB1, 512u);   // consumed at t=1
    }
    // barriers + h0 visible cluster-wide before any remote st.async
    asm volatile("barrier.cluster.arrive.aligned;" ::: "memory");
    asm volatile("barrier.cluster.wait.aligned;" ::: "memory");

    int cur = 0;
    for (int t = 0; t < RNN_T; t++) {
        float xw_nxt = 0.f;
        if (!is_sender && q == 0 && t + 1 < RNN_T)
            xw_nxt = __ldcg(&outn[(size_t)(t + 1) * RNN_H + gc]);

        // partial over my 64 own-half rows (32 packed FFMA2, broadcast LDS)
        const ulonglong2* hp =
            reinterpret_cast<const ulonglong2*>(&hbuf[cur][row0]);
        ull a0 = 0ull, a1 = 0ull;
#pragma unroll
        for (int m = 0; m < 16; m++) {
            ulonglong2 hv = hp[m];           // 4 h values
            ffma2(a0, hv.x, wq[2 * m]);
            ffma2(a1, hv.y, wq[2 * m + 1]);
        }
        float2 f0 = u2f(a0), f1 = u2f(a1);
        float s = (f0.x + f0.y) + (f1.x + f1.y);
        s += __shfl_xor_sync(0xffffffffu, s, 1);          // full 128-row partial
        float s2 = __shfl_down_sync(0xffffffffu, s, 2);   // next col's partial

        if (is_sender) {
            if ((tid & 3) == 0) {            // 64 aggregated sends, 512B total
                ull pkt = f2u(s, s2);
                uint32_t ra = (t & 1) ? rq1 : rq0;
                uint32_t rb = (t & 1) ? rb1 : rb0;
                asm volatile(
                    "st.async.shared::cluster.mbarrier::complete_tx::bytes.b64 [%0], %1, [%2];"
                    :: "r"(ra), "l"(pkt), "r"(rb) : "memory");
            }
        } else if (q == 0) {
            const uint32_t bw = (t & 1) ? mbarB1 : mbarB0;
            mbar_wait(bw, (uint32_t)(t >> 1) & 1u);       // peer partials landed
            if (tid == 0 && t + 2 < RNN_T)                // re-arm for t+2
                mbar_expect(bw, 512u);
            float z = xw_cur + s + qbuf[t & 1][l];
            float e = __expf(2.0f * z);                   // tanh via MUFU
            float hn = 1.0f - __fdividef(2.0f, e + 1.0f);
            if (t + 1 < RNN_T) hbuf[cur ^ 1][l] = hn;     // own h half (local)
            __stcs(&outn[(size_t)t * RNN_H + gc], hn);    // overwrite xW slot
            xw_cur = xw_nxt;
        }
        __syncthreads();   // h_{t+1} visible; all h_t reads complete
        cur ^= 1;
    }

    // keep SMEM alive until all remote traffic has drained cluster-wide
    asm volatile("barrier.cluster.arrive.aligned;" ::: "memory");
    asm volatile("barrier.cluster.wait.aligned;" ::: "memory");
}

// ---------------------------------------------------------------------------
extern "C" void kernel_launch(void* const* d_in, const int* in_sizes, int n_in,
                              void* d_out, int out_size) {
    const float* x  = (const float*)d_in[0];   // [N,T,D]
    const float* h0 = (const float*)d_in[1];   // [N,H]
    const float* Wx = (const float*)d_in[2];   // [D,H]
    const float* Wh = (const float*)d_in[3];   // [H,H]
    const float* b  = (const float*)d_in[4];   // [H]
    float* out = (float*)d_out;                // [N,T,H]

    (void)in_sizes; (void)n_in; (void)out_size;

    dim3 g1((RNN_N * RNN_T) / 128, RNN_H / 128);
    gemm_xw_kernel<<<g1, 256>>>(x, Wx, b, out);

    rnn_scan_kernel<<<RNN_N * 2, 512>>>(h0, Wh, out);
}

// round 16
// speedup vs baseline: 1.4442x; 1.4442x over previous
#include <cuda_runtime.h>
#include <cuda_bf16.h>
#include <cstdint>
#include <cstddef>

// RNN_5188320494079: N=64, T=1024, D=256, H=256, fp32.
// Inputs: x[N,T,D], h0[N,H], Wx[D,H], Wh[H,H], b[H]. Output: [N,T,H].
//
// Kernel 1: Out = x @ Wx + b (packed-f32x2 SGEMM, in-place into d_out).
// Kernel 2: R14-structure cluster scan + poll-storm elimination:
//   - SINGLE-LANE mbarrier waiter (tid 256) + named-barrier release for the
//     other peer-row threads (bar.sync 1) -> ~256x less poll traffic on L1
//   - post-finalize sync shrunk to warps 0-7 only (bar.sync 2); peer-row
//     warps loop straight to their next mbar wait
//   - Ps double-buffered by step parity (closes the WAR race this opens)
//   - everything else from R14: rank-adjusted rows, 64 aggregated b64
//     st.async sends, LDS.128 reduce, double-buffered tx barriers

#define RNN_N 64
#define RNN_T 1024
#define RNN_D 256
#define RNN_H 256
#define HHALF 128

typedef unsigned long long ull;

__device__ __forceinline__ void ffma2(ull& d, ull a, ull b) {
    asm("fma.rn.f32x2 %0, %1, %2, %0;" : "+l"(d) : "l"(a), "l"(b));
}
__device__ __forceinline__ float2 u2f(ull u) {
    float2 f;
    asm("mov.b64 {%0, %1}, %2;" : "=f"(f.x), "=f"(f.y) : "l"(u));
    return f;
}
__device__ __forceinline__ ull f2u(float a, float b) {
    ull u;
    asm("mov.b64 %0, {%1, %2};" : "=l"(u) : "f"(a), "f"(b));
    return u;
}
__device__ __forceinline__ uint32_t smem_u32(const void* p) {
    uint32_t a;
    asm("{ .reg .u64 t; cvta.to.shared.u64 t, %1; cvt.u32.u64 %0, t; }"
        : "=r"(a) : "l"(p));
    return a;
}
__device__ __forceinline__ void mbar_wait(uint32_t addr, uint32_t parity) {
    asm volatile(
        "{\n\t.reg .pred P;\n\t"
        "WL%=:\n\t"
        "mbarrier.try_wait.parity.acquire.cta.shared::cta.b64 P, [%0], %1, 0x989680;\n\t"
        "@P bra.uni WD%=;\n\t"
        "bra.uni WL%=;\n\t"
        "WD%=:\n\t}"
        :: "r"(addr), "r"(parity) : "memory");
}
__device__ __forceinline__ void mbar_expect(uint32_t addr, uint32_t bytes) {
    asm volatile("mbarrier.arrive.expect_tx.shared::cta.b64 _, [%0], %1;"
                 :: "r"(addr), "r"(bytes) : "memory");
}

// ---------------------------------------------------------------------------
// Kernel 1: smem-tiled SGEMM, BM=128 BN=128 BK=16, 256 thr, f32x2 micro-kernel.
// (unchanged — FFMA2-bound, ~190us)
// ---------------------------------------------------------------------------
__global__ __launch_bounds__(256, 2)
void gemm_xw_kernel(const float* __restrict__ X, const float* __restrict__ Wx,
                    const float* __restrict__ bias, float* __restrict__ Out) {
    __shared__ __align__(16) float2 Asd[16][128];
    __shared__ __align__(16) float  Bs[16][128];

    const int tid = threadIdx.x;
    const int tx = tid & 15;
    const int ty = tid >> 4;
    const int m0 = blockIdx.x * 128;
    const int n0 = blockIdx.y * 128;

    const int a_row = tid >> 2;
    const int a_col = (tid & 3) << 2;
    const int b_row = tid >> 5;
    const int b_col = (tid & 31) << 2;

    ull acc[8][4];
#pragma unroll
    for (int i = 0; i < 8; i++)
#pragma unroll
        for (int j = 0; j < 4; j++) acc[i][j] = 0ull;

    const float* Xa0 = &X[(size_t)(m0 + a_row) * RNN_D + a_col];
    const float* Xa1 = &X[(size_t)(m0 + a_row + 64) * RNN_D + a_col];
    const float* Wb0 = &Wx[(size_t)b_row * RNN_H + n0 + b_col];
    const float* Wb1 = &Wx[(size_t)(b_row + 8) * RNN_H + n0 + b_col];

    for (int k0 = 0; k0 < RNN_D; k0 += 16) {
        float4 av0 = __ldcs(reinterpret_cast<const float4*>(Xa0 + k0));
        float4 av1 = __ldcs(reinterpret_cast<const float4*>(Xa1 + k0));
        float4 bv0 = *reinterpret_cast<const float4*>(Wb0 + (size_t)k0 * RNN_H);
        float4 bv1 = *reinterpret_cast<const float4*>(Wb1 + (size_t)k0 * RNN_H);
        __syncthreads();
        Asd[a_col + 0][a_row] = make_float2(av0.x, av0.x);
        Asd[a_col + 1][a_row] = make_float2(av0.y, av0.y);
        Asd[a_col + 2][a_row] = make_float2(av0.z, av0.z);
        Asd[a_col + 3][a_row] = make_float2(av0.w, av0.w);
        Asd[a_col + 0][a_row + 64] = make_float2(av1.x, av1.x);
        Asd[a_col + 1][a_row + 64] = make_float2(av1.y, av1.y);
        Asd[a_col + 2][a_row + 64] = make_float2(av1.z, av1.z);
        Asd[a_col + 3][a_row + 64] = make_float2(av1.w, av1.w);
        *reinterpret_cast<float4*>(&Bs[b_row][b_col]) = bv0;
        *reinterpret_cast<float4*>(&Bs[b_row + 8][b_col]) = bv1;
        __syncthreads();
#pragma unroll
        for (int k = 0; k < 16; k++) {
            const ulonglong2* ad = reinterpret_cast<const ulonglong2*>(&Asd[k][ty * 8]);
            ulonglong2 aa0 = ad[0], aa1 = ad[1], aa2 = ad[2], aa3 = ad[3];
            const ulonglong2* bd = reinterpret_cast<const ulonglong2*>(&Bs[k][tx * 8]);
            ulonglong2 bb0 = bd[0], bb1 = bd[1];
            ull ap[8] = {aa0.x, aa0.y, aa1.x, aa1.y, aa2.x, aa2.y, aa3.x, aa3.y};
            ull bp[4] = {bb0.x, bb0.y, bb1.x, bb1.y};
#pragma unroll
            for (int i = 0; i < 8; i++) {
                ffma2(acc[i][0], ap[i], bp[0]);
                ffma2(acc[i][1], ap[i], bp[1]);
                ffma2(acc[i][2], ap[i], bp[2]);
                ffma2(acc[i][3], ap[i], bp[3]);
            }
        }
    }

    float4 bb0 = *reinterpret_cast<const float4*>(&bias[n0 + tx * 8]);
    float4 bb1 = *reinterpret_cast<const float4*>(&bias[n0 + tx * 8 + 4]);
    float bb[8] = {bb0.x, bb0.y, bb0.z, bb0.w, bb1.x, bb1.y, bb1.z, bb1.w};
#pragma unroll
    for (int i = 0; i < 8; i++) {
        size_t r = (size_t)(m0 + ty * 8 + i) * RNN_H + n0 + tx * 8;
        float2 v0 = u2f(acc[i][0]), v1 = u2f(acc[i][1]);
        float2 v2 = u2f(acc[i][2]), v3 = u2f(acc[i][3]);
        float4 o0 = make_float4(v0.x + bb[0], v0.y + bb[1], v1.x + bb[2], v1.y + bb[3]);
        float4 o1 = make_float4(v2.x + bb[4], v2.y + bb[5], v3.x + bb[6], v3.y + bb[7]);
        *reinterpret_cast<float4*>(&Out[r]) = o0;
        *reinterpret_cast<float4*>(&Out[r + 4]) = o1;
    }
}

// ---------------------------------------------------------------------------
// Kernel 2: cluster scan. Grid 128 CTAs, cluster(2) = batch n, rank r owns
// output cols [r*128,+128). 512 thr: col = tid&127, q = tid>>7;
// ibase = ((q + 2*rank)&3)*64 -> q=0,1 always OWN h rows, q=2,3 peer rows.
// Per thread: Wh[64 rows x 1 col] in regs (32 packed pairs).
// Step t:
//   warps 8-15 (peer rows): tid256 alone waits B[t&1] par ((t-1)>>1)&1 and
//     re-arms; rest released via bar.sync 1 (named barrier, no polling).
//   all: 32 FFMA2 -> Ps[t&1][col][q].   __syncthreads.
//   finalize (tid<128): LDS.128 reduce, tanh, even lanes ship {h,h+1} via
//     64 b64 st.async complete_tx -> peer hbuf[nxt] + B[(t+1)&1]; local
//     hbuf store; __stcs out.   bar.sync 2 (warps 0-7 only).
// ---------------------------------------------------------------------------
__global__ __launch_bounds__(512, 1) __cluster_dims__(2, 1, 1)
void rnn_scan_kernel(const float* __restrict__ h0,
                     const float* __restrict__ Wh,
                     float* Out) {
    __shared__ __align__(16) float hbuf[2][RNN_H];      // full h, 2KB
    __shared__ __align__(16) float Ps[2][HHALF][4];     // partials x2, 4KB
    __shared__ __align__(8)  unsigned long long mbars[2]; // B0, B1

    const int tid = threadIdx.x;
    uint32_t rank;
    asm("mov.u32 %0, %%cluster_ctarank;" : "=r"(rank));
    const uint32_t peer = rank ^ 1u;
    const int n = blockIdx.x >> 1;
    const int col = tid & 127;               // local column
    const int q = tid >> 7;                  // 0..3
    const int ibase = ((q + 2 * (int)rank) & 3) * 64;   // q=0,1 -> own rows
    const bool needs_peer = (q >= 2);
    const int gcol = (int)rank * HHALF + col;            // global column

    const uint32_t mbarB0 = smem_u32((const void*)&mbars[0]);
    const uint32_t mbarB1 = smem_u32((const void*)&mbars[1]);

    if (tid == 0) {
        asm volatile("mbarrier.init.shared.b64 [%0], %1;"
                     :: "r"(mbarB0), "r"(1) : "memory");
        asm volatile("mbarrier.init.shared.b64 [%0], %1;"
                     :: "r"(mbarB1), "r"(1) : "memory");
    }

    // Register Wh slice: rows ibase..ibase+63 x col gcol, 32 packed row-pairs.
    ull wq[32];
#pragma unroll
    for (int k = 0; k < 32; k++) {
        int r = ibase + 2 * k;
        wq[k] = f2u(__ldg(&Wh[(size_t)r * RNN_H + gcol]),
                    __ldg(&Wh[(size_t)(r + 1) * RNN_H + gcol]));
    }

    float* outn = Out + (size_t)n * RNN_T * RNN_H;

    if (tid < RNN_H)
        hbuf[0][tid] = h0[(size_t)n * RNN_H + tid];   // full h0

    // finalize-lane state: xw stream + remote addresses (even lanes send)
    float xw_cur = 0.f;
    uint32_t rH0 = 0, rH1 = 0, rmB0 = 0, rmB1 = 0;
    if (tid < HHALF) {
        xw_cur = __ldcg(&outn[gcol]);
        if ((tid & 1) == 0) {
            uint32_t l0 = smem_u32(&hbuf[0][gcol]);   // 8B-aligned (gcol even)
            uint32_t l1 = smem_u32(&hbuf[1][gcol]);
            asm("mapa.shared::cluster.u32 %0, %1, %2;" : "=r"(rH0) : "r"(l0), "r"(peer));
            asm("mapa.shared::cluster.u32 %0, %1, %2;" : "=r"(rH1) : "r"(l1), "r"(peer));
            asm("mapa.shared::cluster.u32 %0, %1, %2;" : "=r"(rmB0) : "r"(mbarB0), "r"(peer));
            asm("mapa.shared::cluster.u32 %0, %1, %2;" : "=r"(rmB1) : "r"(mbarB1), "r"(peer));
        }
    }
    __syncthreads();
    if (tid == 0) {
        mbar_expect(mbarB1, 512u);   // consumed at t=1 (h_1 arrivals)
        mbar_expect(mbarB0, 512u);   // consumed at t=2 (h_2 arrivals)
    }
    // barriers + h0 visible cluster-wide before any remote st.async
    asm volatile("barrier.cluster.arrive.aligned;" ::: "memory");
    asm volatile("barrier.cluster.wait.aligned;" ::: "memory");

    int cur = 0;
    for (int t = 0; t < RNN_T; t++) {
        float xw_nxt = 0.f;
        if (tid < HHALF && t + 1 < RNN_T)
            xw_nxt = __ldcg(&outn[(size_t)(t + 1) * RNN_H + gcol]);

        // peer-row warps: single-lane mbar wait, named-barrier release
        if (needs_peer && t > 0) {
            if (tid == 256) {
                const uint32_t bw = (t & 1) ? mbarB1 : mbarB0;
                mbar_wait(bw, (uint32_t)((t - 1) >> 1) & 1u);
                if (t + 2 < RNN_T) mbar_expect(bw, 512u);   // re-arm for t+2
            }
            asm volatile("bar.sync 1, 256;" ::: "memory");  // warps 8-15 sleep
        }

        // 32 packed FFMA2 over my 64 rows (broadcast LDS.128 for h)
        const ulonglong2* hp =
            reinterpret_cast<const ulonglong2*>(&hbuf[cur][ibase]);
        ull a0 = 0ull, a1 = 0ull;
#pragma unroll
        for (int m = 0; m < 16; m++) {
            ulonglong2 hv = hp[m];
            ffma2(a0, hv.x, wq[2 * m]);
            ffma2(a1, hv.y, wq[2 * m + 1]);
        }
        float2 f0 = u2f(a0), f1 = u2f(a1);
        Ps[t & 1][col][q] = (f0.x + f0.y) + (f1.x + f1.y);
        __syncthreads();

        const int nxt = cur ^ 1;
        if (tid < HHALF) {
            float4 v = *reinterpret_cast<const float4*>(&Ps[t & 1][col][0]);
            float z = xw_cur + ((v.x + v.y) + (v.z + v.w));
            float e = __expf(2.0f * z);                  // tanh via MUFU
            float hn = 1.0f - __fdividef(2.0f, e + 1.0f);
            if (t + 1 < RNN_T) {
                float hr = __shfl_down_sync(0xffffffffu, hn, 1);
                if ((tid & 1) == 0) {                    // 64 aggregated sends
                    ull pkt = f2u(hn, hr);
                    uint32_t ra = nxt ? rH1 : rH0;
                    uint32_t rb = ((t + 1) & 1) ? rmB1 : rmB0;
                    asm volatile(
                        "st.async.shared::cluster.mbarrier::complete_tx::bytes.b64 [%0], %1, [%2];"
                        :: "r"(ra), "l"(pkt), "r"(rb) : "memory");
                }
                hbuf[nxt][gcol] = hn;                    // local copy
            }
            __stcs(&outn[(size_t)t * RNN_H + gcol], hn); // overwrite xW slot
            xw_cur = xw_nxt;
        }
        if (tid < 256)                                   // warps 0-7 only
            asm volatile("bar.sync 2, 256;" ::: "memory");
        cur ^= 1;
    }

    // keep SMEM alive until all remote traffic has drained cluster-wide
    asm volatile("barrier.cluster.arrive.aligned;" ::: "memory");
    asm volatile("barrier.cluster.wait.aligned;" ::: "memory");
}

// ---------------------------------------------------------------------------
extern "C" void kernel_launch(void* const* d_in, const int* in_sizes, int n_in,
                              void* d_out, int out_size) {
    const float* x  = (const float*)d_in[0];   // [N,T,D]
    const float* h0 = (const float*)d_in[1];   // [N,H]
    const float* Wx = (const float*)d_in[2];   // [D,H]
    const float* Wh = (const float*)d_in[3];   // [H,H]
    const float* b  = (const float*)d_in[4];   // [H]
    float* out = (float*)d_out;                // [N,T,H]

    (void)in_sizes; (void)n_in; (void)out_size;

    dim3 g1((RNN_N * RNN_T) / 128, RNN_H / 128);
    gemm_xw_kernel<<<g1, 256>>>(x, Wx, b, out);

    rnn_scan_kernel<<<RNN_N * 2, 512>>>(h0, Wh, out);
}